// round 6
// baseline (speedup 1.0000x reference)
#include <cuda_runtime.h>
#include <math.h>

#define B_SZ   32
#define D_IN   2
#define L_SEQ  4096
#define H_DIM  128
#define NL     6
#define NC     32
#define D_OUT  2
#define NSEQ   (B_SZ * H_DIM)        // 4096
#define CHUNKS 16
#define CHLEN  (L_SEQ / CHUNKS)      // 256
#define SPT    8                     // states per thread (4 threads per seq-chunk)
#define NG     (SPT / 2)             // packed f32x2 groups per thread = 4
#define GLT    32                    // l-tile for GLU kernel

typedef unsigned long long u64;

// ---------------- f32x2 helpers (sm_103a packed FMA) ----------------
__device__ __forceinline__ u64 pk(float lo, float hi) {
    u64 r;
    asm("mov.b64 %0, {%1, %2};" : "=l"(r) : "r"(__float_as_uint(lo)), "r"(__float_as_uint(hi)));
    return r;
}
__device__ __forceinline__ void upk(u64 a, float& lo, float& hi) {
    unsigned int x, y;
    asm("mov.b64 {%0, %1}, %2;" : "=r"(x), "=r"(y) : "l"(a));
    lo = __uint_as_float(x); hi = __uint_as_float(y);
}
__device__ __forceinline__ u64 fma2(u64 a, u64 b, u64 c) {
    u64 d;
    asm("fma.rn.f32x2 %0, %1, %2, %3;" : "=l"(d) : "l"(a), "l"(b), "l"(c));
    return d;
}
__device__ __forceinline__ u64 mul2(u64 a, u64 b) {
    u64 d;
    asm("mul.rn.f32x2 %0, %1, %2;" : "=l"(d) : "l"(a), "l"(b));
    return d;
}

// ---------------- scratch (static device arrays; no allocation) ----------------
__device__ float  g_h[NSEQ * L_SEQ];                 // current activations (B,H,L)
__device__ float  g_y[NSEQ * L_SEQ];                 // SSM output post-gelu (B,H,L)
__device__ float2 g_E[NSEQ * (CHUNKS - 1) * NC];     // chunk-end states
__device__ float  g_par[NL * 6 * H_DIM * NC];        // wre,wim,c2re,c2im,wpre,wpim
__device__ float  g_Wt[NL * H_DIM * 2 * H_DIM];      // transposed out_W: [layer][k][o]
__device__ float  g_pooled[NSEQ];

// ---------------- per-layer parameter precompute (double for accuracy) ----------
__global__ void param_kernel(const float* __restrict__ log_dt,
                             const float* __restrict__ C_re,
                             const float* __restrict__ C_im,
                             const float* __restrict__ log_A_real,
                             const float* __restrict__ A_imag) {
    int t = blockIdx.x * blockDim.x + threadIdx.x;
    if (t >= NL * H_DIM * NC) return;
    int layer = t / (H_DIM * NC);
    int hn    = t % (H_DIM * NC);
    int h     = hn / NC;

    double dt  = exp((double)log_dt[layer * H_DIM + h]);
    double Are = -exp((double)log_A_real[t]);
    double Aim = (double)A_imag[t];
    double xre = Are * dt, xim = Aim * dt;

    double ex = exp(xre);
    double sy, cy;
    sincos(xim, &sy, &cy);
    double wre = ex * cy, wim = ex * sy;

    double em1re = ex * cy - 1.0;
    double em1im = ex * sy;

    double den = Are * Are + Aim * Aim;
    double fre = (em1re * Are + em1im * Aim) / den;
    double fim = (em1im * Are - em1re * Aim) / den;
    double cre = (double)C_re[t], cim = (double)C_im[t];
    double c2re = 2.0 * (cre * fre - cim * fim);
    double c2im = 2.0 * (cre * fim + cim * fre);

    double pre = exp(xre * (double)CHLEN);
    double ps, pc;
    sincos(xim * (double)CHLEN, &ps, &pc);

    int S = H_DIM * NC;
    int base = layer * 6 * S + hn;
    g_par[base]         = (float)wre;
    g_par[base + S]     = (float)wim;
    g_par[base + 2 * S] = (float)c2re;
    g_par[base + 3 * S] = (float)c2im;
    g_par[base + 4 * S] = (float)(pre * pc);
    g_par[base + 5 * S] = (float)(pre * ps);
}

// ---------------- transpose out_W -> [layer][k][o] ----------------
__global__ void wt_kernel(const float* __restrict__ out_W) {
    int t = blockIdx.x * blockDim.x + threadIdx.x;
    if (t >= NL * 2 * H_DIM * H_DIM) return;
    int layer = t / (2 * H_DIM * H_DIM);
    int r     = t % (2 * H_DIM * H_DIM);
    int o = r / H_DIM;
    int k = r % H_DIM;
    g_Wt[layer * 2 * H_DIM * H_DIM + k * 2 * H_DIM + o] = out_W[t];
}

// ---------------- encoder ----------------
__global__ void enc_kernel(const float* __restrict__ x,
                           const float* __restrict__ enc_W,
                           const float* __restrict__ enc_b) {
    int t = blockIdx.x * blockDim.x + threadIdx.x;
    if (t >= NSEQ * (L_SEQ / 4)) return;
    int l4  = t % (L_SEQ / 4);
    int seq = t / (L_SEQ / 4);
    int b = seq / H_DIM;
    int h = seq % H_DIM;
    float w0 = enc_W[h];
    float w1 = enc_W[H_DIM + h];
    float bb = enc_b[h];
    float4 a = ((const float4*)(x + (b * D_IN + 0) * L_SEQ))[l4];
    float4 c = ((const float4*)(x + (b * D_IN + 1) * L_SEQ))[l4];
    float4 r;
    r.x = fmaf(w1, c.x, fmaf(w0, a.x, bb));
    r.y = fmaf(w1, c.y, fmaf(w0, a.y, bb));
    r.z = fmaf(w1, c.z, fmaf(w0, a.z, bb));
    r.w = fmaf(w1, c.w, fmaf(w0, a.w, bb));
    ((float4*)(g_h + seq * L_SEQ))[l4] = r;
}

// ---------------- pass 1: zero-init chunk-end states, chunks 0..CHUNKS-2 --------
__global__ void pass1_kernel(int layer) {
    int gid  = blockIdx.x * blockDim.x + threadIdx.x;
    int quarter = gid & 3;
    int pair = gid >> 2;
    int chunk = pair % (CHUNKS - 1);
    int seq   = pair / (CHUNKS - 1);
    int h = seq % H_DIM;

    const float* par = g_par + layer * 6 * H_DIM * NC;
    int S  = H_DIM * NC;
    int pb = h * NC + quarter * SPT;

    u64 wre2[NG], wim2[NG], nwim2[NG], sre2[NG], sim2[NG];
#pragma unroll
    for (int g = 0; g < NG; g++) {
        float2 wr = *(const float2*)(par + pb + 2 * g);
        float2 wi = *(const float2*)(par + S + pb + 2 * g);
        wre2[g]  = pk(wr.x, wr.y);
        wim2[g]  = pk(wi.x, wi.y);
        nwim2[g] = pk(-wi.x, -wi.y);
        sre2[g] = 0ull; sim2[g] = 0ull;
    }

    const float4* u4 = (const float4*)(g_h + seq * L_SEQ + chunk * CHLEN);
    for (int l = 0; l < CHLEN / 4; l++) {
        float4 u = u4[l];
        float uu[4] = {u.x, u.y, u.z, u.w};
#pragma unroll
        for (int q = 0; q < 4; q++) {
            u64 u2 = pk(uu[q], uu[q]);
#pragma unroll
            for (int g = 0; g < NG; g++) {
                u64 nr = fma2(nwim2[g], sim2[g], fma2(wre2[g], sre2[g], u2));
                u64 ni = fma2(wre2[g], sim2[g], mul2(wim2[g], sre2[g]));
                sre2[g] = nr; sim2[g] = ni;
            }
        }
    }

    float2* E = g_E + (seq * (CHUNKS - 1) + chunk) * NC + quarter * SPT;
#pragma unroll
    for (int g = 0; g < NG; g++) {
        float r0, r1, i0, i1;
        upk(sre2[g], r0, r1);
        upk(sim2[g], i0, i1);
        E[2 * g]     = make_float2(r0, i0);
        E[2 * g + 1] = make_float2(r1, i1);
    }
}

// ---------------- pass 2: exact recurrence + D skip + gelu -> g_y ----------------
// Epilogue: butterfly transpose-reduce so lane q of each 4-lane group finishes
// element 4l+q alone (1 erff per 4 elements per lane).
__global__ void pass2_kernel(int layer, const float* __restrict__ Dvec) {
    int gid  = blockIdx.x * blockDim.x + threadIdx.x;
    int quarter = gid & 3;
    int rest = gid >> 2;
    int chunk = rest % CHUNKS;
    int seq   = rest / CHUNKS;
    int h = seq % H_DIM;

    const float* par = g_par + layer * 6 * H_DIM * NC;
    int S  = H_DIM * NC;
    int pb = h * NC + quarter * SPT;

    u64 sre2[NG], sim2[NG];
#pragma unroll
    for (int g = 0; g < NG; g++) { sre2[g] = 0ull; sim2[g] = 0ull; }

    if (chunk > 0) {
        u64 wpre2[NG], wpim2[NG], nwpim2[NG];
#pragma unroll
        for (int g = 0; g < NG; g++) {
            float2 wr = *(const float2*)(par + 4 * S + pb + 2 * g);
            float2 wi = *(const float2*)(par + 5 * S + pb + 2 * g);
            wpre2[g]  = pk(wr.x, wr.y);
            wpim2[g]  = pk(wi.x, wi.y);
            nwpim2[g] = pk(-wi.x, -wi.y);
        }
        for (int c = 0; c < chunk; c++) {
            const float2* E = g_E + (seq * (CHUNKS - 1) + c) * NC + quarter * SPT;
#pragma unroll
            for (int g = 0; g < NG; g++) {
                float2 e0 = E[2 * g], e1 = E[2 * g + 1];
                u64 re2 = pk(e0.x, e1.x);
                u64 im2 = pk(e0.y, e1.y);
                u64 nr = fma2(wpre2[g], sre2[g], fma2(nwpim2[g], sim2[g], re2));
                u64 ni = fma2(wpre2[g], sim2[g], fma2(wpim2[g], sre2[g], im2));
                sre2[g] = nr; sim2[g] = ni;
            }
        }
    }

    u64 wre2[NG], wim2[NG], nwim2[NG], cr2[NG], nci2[NG];
#pragma unroll
    for (int g = 0; g < NG; g++) {
        float2 wr = *(const float2*)(par + pb + 2 * g);
        float2 wi = *(const float2*)(par + S + pb + 2 * g);
        float2 cr = *(const float2*)(par + 2 * S + pb + 2 * g);
        float2 ci = *(const float2*)(par + 3 * S + pb + 2 * g);
        wre2[g]  = pk(wr.x, wr.y);
        wim2[g]  = pk(wi.x, wi.y);
        nwim2[g] = pk(-wi.x, -wi.y);
        cr2[g]   = pk(cr.x, cr.y);
        nci2[g]  = pk(-ci.x, -ci.y);
    }
    float Dh = Dvec[layer * H_DIM + h];

    const float4* u4 = (const float4*)(g_h + seq * L_SEQ + chunk * CHLEN);
    float*        yp = g_y + seq * L_SEQ + chunk * CHLEN;

    int  q1 = quarter & 1;
    bool q2 = (quarter & 2) != 0;

    for (int l = 0; l < CHLEN / 4; l++) {
        float4 u = u4[l];
        float uu[4] = {u.x, u.y, u.z, u.w};
        float s[4];
#pragma unroll
        for (int q = 0; q < 4; q++) {
            float uv = uu[q];
            u64 u2 = pk(uv, uv);
            u64 acc2 = 0ull;
#pragma unroll
            for (int g = 0; g < NG; g++) {
                u64 nr = fma2(nwim2[g], sim2[g], fma2(wre2[g], sre2[g], u2));
                u64 ni = fma2(wre2[g], sim2[g], mul2(wim2[g], sre2[g]));
                sre2[g] = nr; sim2[g] = ni;
                acc2 = fma2(cr2[g], nr, acc2);
                acc2 = fma2(nci2[g], ni, acc2);
            }
            float alo, ahi;
            upk(acc2, alo, ahi);
            s[q] = alo + ahi;
        }
        // butterfly transpose-reduce across the 4-lane group
        float sA = q1 ? s[1] : s[0];
        float sB = q1 ? s[0] : s[1];
        float sC = q1 ? s[3] : s[2];
        float sD = q1 ? s[2] : s[3];
        float p0 = sA + __shfl_xor_sync(0xffffffffu, sB, 1);
        float p1 = sC + __shfl_xor_sync(0xffffffffu, sD, 1);
        float send2 = q2 ? p0 : p1;
        float tot = (q2 ? p1 : p0) + __shfl_xor_sync(0xffffffffu, send2, 2);
        float ua = q1 ? uu[1] : uu[0];
        float ub = q1 ? uu[3] : uu[2];
        float um = q2 ? ub : ua;
        float yv = fmaf(um, Dh, tot);
        float gl = 0.5f * yv * (1.f + erff(yv * 0.7071067811865476f));
        yp[4 * l + quarter] = gl;
    }
}

// -------- GLU GEMM + residual + LayerNorm; GLT=32 l-tile, aliased smem ----------
__global__ void __launch_bounds__(256) glu_kernel(int layer,
                           const float* __restrict__ out_b,
                           const float* __restrict__ ln_g,
                           const float* __restrict__ ln_b) {
    __shared__ float  ys[H_DIM][GLT];       // y tile [k][l]  16KB (reused as agA)
    __shared__ float  agG[GLT][H_DIM];      // gate transpose 16KB
    __shared__ float2 mv[GLT];

    float (*agA)[H_DIM] = (float(*)[H_DIM])ys;   // alias: A/z transpose [l][ch]

    int bl = blockIdx.x;
    int b  = bl / (L_SEQ / GLT);
    int l0 = (bl % (L_SEQ / GLT)) * GLT;
    int t  = threadIdx.x;                   // 256

    // stage y tile: 2 threads per row k, 16 floats each
    {
        int k = t >> 1, hf = t & 1;
        const float4* src = (const float4*)(g_y + (b * H_DIM + k) * L_SEQ + l0 + hf * 16);
        float4* dst = (float4*)&ys[k][hf * 16];
        dst[0] = __ldg(src);
        dst[1] = __ldg(src + 1);
        dst[2] = __ldg(src + 2);
        dst[3] = __ldg(src + 3);
    }
    __syncthreads();

    float bias = out_b[layer * 2 * H_DIM + t];
    u64 acc[16];
#pragma unroll
    for (int g = 0; g < 16; g++) acc[g] = pk(bias, bias);

    const float* wrow = g_Wt + layer * 2 * H_DIM * H_DIM + t;
#pragma unroll 2
    for (int k = 0; k < H_DIM; k++) {
        float w = __ldg(wrow + k * 2 * H_DIM);
        u64 w2 = pk(w, w);
        const ulonglong2* yr = (const ulonglong2*)&ys[k][0];
#pragma unroll
        for (int i = 0; i < 8; i++) {
            ulonglong2 q = yr[i];
            acc[2 * i]     = fma2(w2, q.x, acc[2 * i]);
            acc[2 * i + 1] = fma2(w2, q.y, acc[2 * i + 1]);
        }
    }
    __syncthreads();   // everyone done reading ys before A overlays it

    // scatter: A rows (t<128) into agA(=ys), G rows into agG
    {
        int ch = t & 127;
        if (t < 128) {
#pragma unroll
            for (int g = 0; g < 16; g++) {
                float v0, v1;
                upk(acc[g], v0, v1);
                agA[2 * g][ch]     = v0;
                agA[2 * g + 1][ch] = v1;
            }
        } else {
#pragma unroll
            for (int g = 0; g < 16; g++) {
                float v0, v1;
                upk(acc[g], v0, v1);
                agG[2 * g][ch]     = v0;
                agG[2 * g + 1][ch] = v1;
            }
        }
    }
    __syncthreads();

    // GLU + residual
    {
        int ch = t & 127, lh = t >> 7;
        const float4* hp = (const float4*)(g_h + (b * H_DIM + ch) * L_SEQ + l0 + lh * 16);
        float hv[16];
#pragma unroll
        for (int i = 0; i < 4; i++) ((float4*)hv)[i] = hp[i];
#pragma unroll
        for (int i = 0; i < 16; i++) {
            int l = lh * 16 + i;
            float a   = agA[l][ch];
            float gte = agG[l][ch];
            float sg  = 1.f / (1.f + expf(-gte));
            agA[l][ch] = fmaf(a, sg, hv[i]);    // z = GLU + residual (in place)
        }
    }
    __syncthreads();

    // LayerNorm stats per l
    {
        int w = t >> 5, lane = t & 31;
#pragma unroll
        for (int l = w; l < GLT; l += 8) {
            float v0 = agA[l][lane],      v1 = agA[l][lane + 32];
            float v2 = agA[l][lane + 64], v3 = agA[l][lane + 96];
            float s = v0 + v1 + v2 + v3;
            float q = fmaf(v0, v0, fmaf(v1, v1, fmaf(v2, v2, v3 * v3)));
#pragma unroll
            for (int off = 16; off > 0; off >>= 1) {
                s += __shfl_xor_sync(0xffffffffu, s, off);
                q += __shfl_xor_sync(0xffffffffu, q, off);
            }
            if (lane == 0) {
                float m   = s * (1.0f / H_DIM);
                float var = q * (1.0f / H_DIM) - m * m;
                mv[l] = make_float2(m, rsqrtf(var + 1e-5f));
            }
        }
    }
    __syncthreads();

    // normalize + write back
    {
        int ch = t & 127, lh = t >> 7;
        float gam = ln_g[layer * H_DIM + ch];
        float bet = ln_b[layer * H_DIM + ch];
        float r[16];
#pragma unroll
        for (int i = 0; i < 16; i++) {
            int l = lh * 16 + i;
            float2 m = mv[l];
            r[i] = fmaf((agA[l][ch] - m.x) * m.y, gam, bet);
        }
        float4* wp = (float4*)(g_h + (b * H_DIM + ch) * L_SEQ + l0 + lh * 16);
#pragma unroll
        for (int i = 0; i < 4; i++) wp[i] = ((float4*)r)[i];
    }
}

// ---------------- mean over L ----------------
__global__ void pool_kernel() {
    int seq = blockIdx.x;
    int t   = threadIdx.x;    // 256 threads
    const float4* r = (const float4*)(g_h + seq * L_SEQ);
    float s = 0.f;
    for (int i = t; i < L_SEQ / 4; i += 256) {
        float4 v = r[i];
        s += v.x + v.y + v.z + v.w;
    }
    __shared__ float sm[256];
    sm[t] = s;
    __syncthreads();
    for (int off = 128; off > 0; off >>= 1) {
        if (t < off) sm[t] += sm[t + off];
        __syncthreads();
    }
    if (t == 0) g_pooled[seq] = sm[0] * (1.f / L_SEQ);
}

// ---------------- head ----------------
__global__ void head_kernel(const float* __restrict__ head_W,
                            const float* __restrict__ head_b,
                            float* __restrict__ out) {
    int t = threadIdx.x;
    if (t >= B_SZ * D_OUT) return;
    int b = t / D_OUT, o = t % D_OUT;
    float s = head_b[o];
    for (int h = 0; h < H_DIM; h++)
        s = fmaf(g_pooled[b * H_DIM + h], head_W[h * D_OUT + o], s);
    out[t] = s;
}

// ---------------- launch ----------------
extern "C" void kernel_launch(void* const* d_in, const int* in_sizes, int n_in,
                              void* d_out, int out_size) {
    const float* x          = (const float*)d_in[0];
    const float* enc_W      = (const float*)d_in[1];
    const float* enc_b      = (const float*)d_in[2];
    const float* log_dt     = (const float*)d_in[3];
    const float* C_re       = (const float*)d_in[4];
    const float* C_im       = (const float*)d_in[5];
    const float* log_A_real = (const float*)d_in[6];
    const float* A_imag     = (const float*)d_in[7];
    const float* Dvec       = (const float*)d_in[8];
    const float* out_W      = (const float*)d_in[9];
    const float* out_b      = (const float*)d_in[10];
    const float* ln_g       = (const float*)d_in[11];
    const float* ln_b       = (const float*)d_in[12];
    const float* head_W     = (const float*)d_in[13];
    const float* head_b     = (const float*)d_in[14];
    float* out = (float*)d_out;

    param_kernel<<<(NL * H_DIM * NC + 127) / 128, 128>>>(log_dt, C_re, C_im,
                                                         log_A_real, A_imag);
    wt_kernel<<<(NL * 2 * H_DIM * H_DIM + 255) / 256, 256>>>(out_W);
    enc_kernel<<<(NSEQ * (L_SEQ / 4)) / 256, 256>>>(x, enc_W, enc_b);

    for (int layer = 0; layer < NL; layer++) {
        pass1_kernel<<<(NSEQ * (CHUNKS - 1) * 4) / 128, 128>>>(layer);
        pass2_kernel<<<(NSEQ * CHUNKS * 4) / 128, 128>>>(layer, Dvec);
        glu_kernel<<<B_SZ * (L_SEQ / GLT), 256>>>(layer, out_b, ln_g, ln_b);
    }

    pool_kernel<<<NSEQ, 256>>>();
    head_kernel<<<1, 64>>>(head_W, head_b, out);
}

// round 8
// speedup vs baseline: 1.1805x; 1.1805x over previous
#include <cuda_runtime.h>
#include <cuda_bf16.h>
#include <math.h>

#define B_SZ   32
#define D_IN   2
#define L_SEQ  4096
#define H_DIM  128
#define NL     6
#define NC     32
#define D_OUT  2
#define NSEQ   (B_SZ * H_DIM)        // 4096
#define CHUNKS 16
#define CHLEN  (L_SEQ / CHUNKS)      // 256
#define SPT    8
#define NG     (SPT / 2)

typedef unsigned long long u64;
typedef unsigned int u32;

// ---------------- f32x2 helpers ----------------
__device__ __forceinline__ u64 pk(float lo, float hi) {
    u64 r;
    asm("mov.b64 %0, {%1, %2};" : "=l"(r) : "r"(__float_as_uint(lo)), "r"(__float_as_uint(hi)));
    return r;
}
__device__ __forceinline__ void upk(u64 a, float& lo, float& hi) {
    u32 x, y;
    asm("mov.b64 {%0, %1}, %2;" : "=r"(x), "=r"(y) : "l"(a));
    lo = __uint_as_float(x); hi = __uint_as_float(y);
}
__device__ __forceinline__ u64 fma2(u64 a, u64 b, u64 c) {
    u64 d;
    asm("fma.rn.f32x2 %0, %1, %2, %3;" : "=l"(d) : "l"(a), "l"(b), "l"(c));
    return d;
}
__device__ __forceinline__ u64 mul2(u64 a, u64 b) {
    u64 d;
    asm("mul.rn.f32x2 %0, %1, %2;" : "=l"(d) : "l"(a), "l"(b));
    return d;
}

// ---------------- tensor-core helpers (baseline sm_90+/103 ISA) ----------------
__device__ __forceinline__ unsigned smaddr(const void* p) {
    unsigned a;
    asm("{ .reg .u64 t; cvta.to.shared.u64 t, %1; cvt.u32.u64 %0, t; }" : "=r"(a) : "l"(p));
    return a;
}
__device__ __forceinline__ void ldm_x4(u32& r0, u32& r1, u32& r2, u32& r3, unsigned addr) {
    asm volatile("ldmatrix.sync.aligned.m8n8.x4.shared.b16 {%0,%1,%2,%3}, [%4];"
                 : "=r"(r0), "=r"(r1), "=r"(r2), "=r"(r3) : "r"(addr));
}
__device__ __forceinline__ void mma_bf16(float* c, u32 a0, u32 a1, u32 a2, u32 a3,
                                         u32 b0, u32 b1) {
    asm volatile(
        "mma.sync.aligned.m16n8k16.row.col.f32.bf16.bf16.f32 "
        "{%0,%1,%2,%3}, {%4,%5,%6,%7}, {%8,%9}, {%0,%1,%2,%3};"
        : "+f"(c[0]), "+f"(c[1]), "+f"(c[2]), "+f"(c[3])
        : "r"(a0), "r"(a1), "r"(a2), "r"(a3), "r"(b0), "r"(b1));
}
__device__ __forceinline__ u32 bf16x2pk(float lo, float hi) {
    u32 r;
    asm("cvt.rn.bf16x2.f32 %0, %1, %2;" : "=r"(r) : "f"(hi), "f"(lo));
    return r;
}

// smem layout for glu_mma (dynamic). Row pitch = 272B (136 bf16) -> conflict-free.
#define WPITCH 272
#define SM_WHI 0
#define SM_WLO 69632
#define SM_X   139264               // Yhi here; zAG overlays after MMA
#define SM_AHI SM_X
#define SM_ALO (SM_X + 17408)
#define ZPITCH 132                  // floats
#define SM_MV  (SM_X + 67584)       // 64 x float2
#define SMEM_MMA (SM_MV + 512)      // 207360 bytes

#define GLT 64                      // l-tile
#define TILES_PER_BLK 4

// ---------------- scratch ----------------
__device__ float  g_h[NSEQ * L_SEQ];
__device__ float  g_y[NSEQ * L_SEQ];
__device__ float2 g_E[NSEQ * (CHUNKS - 1) * NC];
__device__ float  g_par[NL * 6 * H_DIM * NC];
__device__ __nv_bfloat16 g_Whi[NL * 2 * H_DIM * H_DIM];
__device__ __nv_bfloat16 g_Wlo[NL * 2 * H_DIM * H_DIM];
__device__ float  g_pooled[NSEQ];

// ---------------- parameter precompute ----------------
__global__ void param_kernel(const float* __restrict__ log_dt,
                             const float* __restrict__ C_re,
                             const float* __restrict__ C_im,
                             const float* __restrict__ log_A_real,
                             const float* __restrict__ A_imag) {
    int t = blockIdx.x * blockDim.x + threadIdx.x;
    if (t >= NL * H_DIM * NC) return;
    int layer = t / (H_DIM * NC);
    int hn    = t % (H_DIM * NC);
    int h     = hn / NC;

    double dt  = exp((double)log_dt[layer * H_DIM + h]);
    double Are = -exp((double)log_A_real[t]);
    double Aim = (double)A_imag[t];
    double xre = Are * dt, xim = Aim * dt;

    double ex = exp(xre);
    double sy, cy;
    sincos(xim, &sy, &cy);
    double wre = ex * cy, wim = ex * sy;

    double em1re = ex * cy - 1.0;
    double em1im = ex * sy;

    double den = Are * Are + Aim * Aim;
    double fre = (em1re * Are + em1im * Aim) / den;
    double fim = (em1im * Are - em1re * Aim) / den;
    double cre = (double)C_re[t], cim = (double)C_im[t];
    double c2re = 2.0 * (cre * fre - cim * fim);
    double c2im = 2.0 * (cre * fim + cim * fre);

    double pre = exp(xre * (double)CHLEN);
    double ps, pc;
    sincos(xim * (double)CHLEN, &ps, &pc);

    int S = H_DIM * NC;
    int base = layer * 6 * S + hn;
    g_par[base]         = (float)wre;
    g_par[base + S]     = (float)wim;
    g_par[base + 2 * S] = (float)c2re;
    g_par[base + 3 * S] = (float)c2im;
    g_par[base + 4 * S] = (float)(pre * pc);
    g_par[base + 5 * S] = (float)(pre * ps);
}

// ---------------- weight hi/lo bf16 split ----------------
__global__ void wsplit_kernel(const float* __restrict__ out_W) {
    int t = blockIdx.x * blockDim.x + threadIdx.x;
    if (t >= NL * 2 * H_DIM * H_DIM) return;
    float x = out_W[t];
    __nv_bfloat16 hi = __float2bfloat16(x);
    __nv_bfloat16 lo = __float2bfloat16(x - __bfloat162float(hi));
    g_Whi[t] = hi;
    g_Wlo[t] = lo;
}

// ---------------- encoder ----------------
__global__ void enc_kernel(const float* __restrict__ x,
                           const float* __restrict__ enc_W,
                           const float* __restrict__ enc_b) {
    int t = blockIdx.x * blockDim.x + threadIdx.x;
    if (t >= NSEQ * (L_SEQ / 4)) return;
    int l4  = t % (L_SEQ / 4);
    int seq = t / (L_SEQ / 4);
    int b = seq / H_DIM;
    int h = seq % H_DIM;
    float w0 = enc_W[h];
    float w1 = enc_W[H_DIM + h];
    float bb = enc_b[h];
    float4 a = ((const float4*)(x + (b * D_IN + 0) * L_SEQ))[l4];
    float4 c = ((const float4*)(x + (b * D_IN + 1) * L_SEQ))[l4];
    float4 r;
    r.x = fmaf(w1, c.x, fmaf(w0, a.x, bb));
    r.y = fmaf(w1, c.y, fmaf(w0, a.y, bb));
    r.z = fmaf(w1, c.z, fmaf(w0, a.z, bb));
    r.w = fmaf(w1, c.w, fmaf(w0, a.w, bb));
    ((float4*)(g_h + seq * L_SEQ))[l4] = r;
}

// ---------------- pass 1 ----------------
__global__ void pass1_kernel(int layer) {
    int gid  = blockIdx.x * blockDim.x + threadIdx.x;
    int quarter = gid & 3;
    int pair = gid >> 2;
    int chunk = pair % (CHUNKS - 1);
    int seq   = pair / (CHUNKS - 1);
    int h = seq % H_DIM;

    const float* par = g_par + layer * 6 * H_DIM * NC;
    int S  = H_DIM * NC;
    int pb = h * NC + quarter * SPT;

    u64 wre2[NG], wim2[NG], nwim2[NG], sre2[NG], sim2[NG];
#pragma unroll
    for (int g = 0; g < NG; g++) {
        float2 wr = *(const float2*)(par + pb + 2 * g);
        float2 wi = *(const float2*)(par + S + pb + 2 * g);
        wre2[g]  = pk(wr.x, wr.y);
        wim2[g]  = pk(wi.x, wi.y);
        nwim2[g] = pk(-wi.x, -wi.y);
        sre2[g] = 0ull; sim2[g] = 0ull;
    }

    const float4* u4 = (const float4*)(g_h + seq * L_SEQ + chunk * CHLEN);
    for (int l = 0; l < CHLEN / 4; l++) {
        float4 u = u4[l];
        float uu[4] = {u.x, u.y, u.z, u.w};
#pragma unroll
        for (int q = 0; q < 4; q++) {
            u64 u2 = pk(uu[q], uu[q]);
#pragma unroll
            for (int g = 0; g < NG; g++) {
                u64 nr = fma2(nwim2[g], sim2[g], fma2(wre2[g], sre2[g], u2));
                u64 ni = fma2(wre2[g], sim2[g], mul2(wim2[g], sre2[g]));
                sre2[g] = nr; sim2[g] = ni;
            }
        }
    }

    float2* E = g_E + (seq * (CHUNKS - 1) + chunk) * NC + quarter * SPT;
#pragma unroll
    for (int g = 0; g < NG; g++) {
        float r0, r1, i0, i1;
        upk(sre2[g], r0, r1);
        upk(sim2[g], i0, i1);
        E[2 * g]     = make_float2(r0, i0);
        E[2 * g + 1] = make_float2(r1, i1);
    }
}

// ---------------- pass 2 ----------------
__global__ void pass2_kernel(int layer, const float* __restrict__ Dvec) {
    int gid  = blockIdx.x * blockDim.x + threadIdx.x;
    int quarter = gid & 3;
    int rest = gid >> 2;
    int chunk = rest % CHUNKS;
    int seq   = rest / CHUNKS;
    int h = seq % H_DIM;

    const float* par = g_par + layer * 6 * H_DIM * NC;
    int S  = H_DIM * NC;
    int pb = h * NC + quarter * SPT;

    u64 sre2[NG], sim2[NG];
#pragma unroll
    for (int g = 0; g < NG; g++) { sre2[g] = 0ull; sim2[g] = 0ull; }

    if (chunk > 0) {
        u64 wpre2[NG], wpim2[NG], nwpim2[NG];
#pragma unroll
        for (int g = 0; g < NG; g++) {
            float2 wr = *(const float2*)(par + 4 * S + pb + 2 * g);
            float2 wi = *(const float2*)(par + 5 * S + pb + 2 * g);
            wpre2[g]  = pk(wr.x, wr.y);
            wpim2[g]  = pk(wi.x, wi.y);
            nwpim2[g] = pk(-wi.x, -wi.y);
        }
        for (int c = 0; c < chunk; c++) {
            const float2* E = g_E + (seq * (CHUNKS - 1) + c) * NC + quarter * SPT;
#pragma unroll
            for (int g = 0; g < NG; g++) {
                float2 e0 = E[2 * g], e1 = E[2 * g + 1];
                u64 re2 = pk(e0.x, e1.x);
                u64 im2 = pk(e0.y, e1.y);
                u64 nr = fma2(wpre2[g], sre2[g], fma2(nwpim2[g], sim2[g], re2));
                u64 ni = fma2(wpre2[g], sim2[g], fma2(wpim2[g], sre2[g], im2));
                sre2[g] = nr; sim2[g] = ni;
            }
        }
    }

    u64 wre2[NG], wim2[NG], nwim2[NG], cr2[NG], nci2[NG];
#pragma unroll
    for (int g = 0; g < NG; g++) {
        float2 wr = *(const float2*)(par + pb + 2 * g);
        float2 wi = *(const float2*)(par + S + pb + 2 * g);
        float2 cr = *(const float2*)(par + 2 * S + pb + 2 * g);
        float2 ci = *(const float2*)(par + 3 * S + pb + 2 * g);
        wre2[g]  = pk(wr.x, wr.y);
        wim2[g]  = pk(wi.x, wi.y);
        nwim2[g] = pk(-wi.x, -wi.y);
        cr2[g]   = pk(cr.x, cr.y);
        nci2[g]  = pk(-ci.x, -ci.y);
    }
    float Dh = Dvec[layer * H_DIM + h];

    const float4* u4 = (const float4*)(g_h + seq * L_SEQ + chunk * CHLEN);
    float*        yp = g_y + seq * L_SEQ + chunk * CHLEN;

    int  q1 = quarter & 1;
    bool q2 = (quarter & 2) != 0;

    for (int l = 0; l < CHLEN / 4; l++) {
        float4 u = u4[l];
        float uu[4] = {u.x, u.y, u.z, u.w};
        float s[4];
#pragma unroll
        for (int q = 0; q < 4; q++) {
            float uv = uu[q];
            u64 u2 = pk(uv, uv);
            u64 acc2 = 0ull;
#pragma unroll
            for (int g = 0; g < NG; g++) {
                u64 nr = fma2(nwim2[g], sim2[g], fma2(wre2[g], sre2[g], u2));
                u64 ni = fma2(wre2[g], sim2[g], mul2(wim2[g], sre2[g]));
                sre2[g] = nr; sim2[g] = ni;
                acc2 = fma2(cr2[g], nr, acc2);
                acc2 = fma2(nci2[g], ni, acc2);
            }
            float alo, ahi;
            upk(acc2, alo, ahi);
            s[q] = alo + ahi;
        }
        float sA = q1 ? s[1] : s[0];
        float sB = q1 ? s[0] : s[1];
        float sC = q1 ? s[3] : s[2];
        float sD = q1 ? s[2] : s[3];
        float p0 = sA + __shfl_xor_sync(0xffffffffu, sB, 1);
        float p1 = sC + __shfl_xor_sync(0xffffffffu, sD, 1);
        float send2 = q2 ? p0 : p1;
        float tot = (q2 ? p1 : p0) + __shfl_xor_sync(0xffffffffu, send2, 2);
        float ua = q1 ? uu[1] : uu[0];
        float ub = q1 ? uu[3] : uu[2];
        float um = q2 ? ub : ua;
        float yv = fmaf(um, Dh, tot);
        float gl = 0.5f * yv * (1.f + erff(yv * 0.7071067811865476f));
        yp[4 * l + quarter] = gl;
    }
}

// ======== GLU via mma.sync bf16 split-precision + fused GLU/residual/LN ========
// Block: 256 threads (8 warps). Grid: 512. Each block: stage Whi+Wlo once,
// then 4 l-tiles of 64: stage Y hi/lo, 3 GEMM passes, epilogue.
__global__ void __launch_bounds__(256) glu_mma_kernel(int layer,
                           const float* __restrict__ out_b,
                           const float* __restrict__ ln_g,
                           const float* __restrict__ ln_b) {
    extern __shared__ char smem[];
    unsigned sb = smaddr(smem);
    int tid = threadIdx.x;
    int w = tid >> 5, lane = tid & 31;

    int b   = blockIdx.x >> 4;
    int seg = blockIdx.x & 15;

    // ---- stage W (hi and lo), pitch 272B ----
    {
        const uint4* shi = (const uint4*)(g_Whi + layer * 2 * H_DIM * H_DIM);
        const uint4* slo = (const uint4*)(g_Wlo + layer * 2 * H_DIM * H_DIM);
#pragma unroll
        for (int it = 0; it < 16; it++) {
            int idx = tid + it * 256;          // 4096 chunks of 16B
            int o = idx >> 4, c = idx & 15;
            *(uint4*)(smem + SM_WHI + o * WPITCH + c * 16) = __ldg(shi + idx);
            *(uint4*)(smem + SM_WLO + o * WPITCH + c * 16) = __ldg(slo + idx);
        }
    }

    int mbase = (w & 3) * 16;
    int nbase = (w >> 2) * 128;
    int sel   = lane >> 3;
    int arow  = mbase + (lane & 7) + (sel & 1) * 8;
    int akadd = (sel >> 1) * 8;
    int brow0 = (lane & 7) + (sel >> 1) * 8;
    int bkadd = (sel & 1) * 8;

    for (int tl = 0; tl < TILES_PER_BLK; tl++) {
        int l0 = seg * 256 + tl * 64;
        __syncthreads();   // W staged / previous tile's epilogue done

        // ---- stage Y tile: A[l][k] bf16 hi/lo, pitch 272B ----
#pragma unroll
        for (int it = 0; it < 16; it++) {
            int idx = tid + it * 256;          // 4096 = 64 l x 64 kpairs
            int l = idx & 63, kp = idx >> 6;
            const float* r0 = g_y + (b * H_DIM + 2 * kp) * L_SEQ + l0;
            const float* r1 = r0 + L_SEQ;
            float f0 = __ldg(r0 + l);
            float f1 = __ldg(r1 + l);
            float h0 = __bfloat162float(__float2bfloat16(f0));
            float h1 = __bfloat162float(__float2bfloat16(f1));
            *(u32*)(smem + SM_AHI + l * WPITCH + kp * 4) = bf16x2pk(f0, f1);
            *(u32*)(smem + SM_ALO + l * WPITCH + kp * 4) = bf16x2pk(f0 - h0, f1 - h1);
        }
        __syncthreads();

        // ---- 3 GEMM passes into shared fp32 accumulators ----
        float acc[16][4];
#pragma unroll
        for (int n = 0; n < 16; n++)
#pragma unroll
            for (int j = 0; j < 4; j++) acc[n][j] = 0.f;

#pragma unroll
        for (int p = 0; p < 3; p++) {
            unsigned abase = sb + (p == 1 ? SM_ALO : SM_AHI);
            unsigned wbase = sb + (p == 2 ? SM_WLO : SM_WHI);
#pragma unroll
            for (int ks = 0; ks < 8; ks++) {
                u32 a0, a1, a2, a3;
                ldm_x4(a0, a1, a2, a3,
                       abase + arow * WPITCH + (ks * 16 + akadd) * 2);
#pragma unroll
                for (int nt2 = 0; nt2 < 8; nt2++) {
                    u32 b0, b1, b2, b3;
                    int nrow = nbase + nt2 * 16 + brow0;
                    ldm_x4(b0, b1, b2, b3,
                           wbase + nrow * WPITCH + (ks * 16 + bkadd) * 2);
                    mma_bf16(acc[2 * nt2],     a0, a1, a2, a3, b0, b1);
                    mma_bf16(acc[2 * nt2 + 1], a0, a1, a2, a3, b2, b3);
                }
            }
        }
        __syncthreads();   // all warps done reading Y before zAG overlays it

        // ---- scatter frags (+bias) to zAG[sel][l][o], pitch 132 floats ----
        {
            float* zbase = (float*)(smem + SM_X) + (w >> 2) * GLT * ZPITCH;
            const float* ob = out_b + layer * 2 * H_DIM + nbase;
            int lrow = mbase + (lane >> 2);
            int ncol = 2 * (lane & 3);
#pragma unroll
            for (int nt = 0; nt < 16; nt++) {
                int n = nt * 8 + ncol;
                float b0 = __ldg(ob + n), b1 = __ldg(ob + n + 1);
                *(float2*)(zbase + lrow * ZPITCH + n) =
                    make_float2(acc[nt][0] + b0, acc[nt][1] + b1);
                *(float2*)(zbase + (lrow + 8) * ZPITCH + n) =
                    make_float2(acc[nt][2] + b0, acc[nt][3] + b1);
            }
        }
        __syncthreads();

        // ---- GLU + residual (in place into zA) ----
        {
            int ch = tid & 127, lh = tid >> 7;   // 32 l's each
            float* zA = (float*)(smem + SM_X);
            float* zG = zA + GLT * ZPITCH;
            const float* hp = g_h + (b * H_DIM + ch) * L_SEQ + l0 + lh * 32;
            float hv[32];
#pragma unroll
            for (int i = 0; i < 8; i++) ((float4*)hv)[i] = __ldg((const float4*)hp + i);
#pragma unroll
            for (int i = 0; i < 32; i++) {
                int l = lh * 32 + i;
                float a = zA[l * ZPITCH + ch];
                float g = zG[l * ZPITCH + ch];
                zA[l * ZPITCH + ch] = fmaf(a, 1.f / (1.f + expf(-g)), hv[i]);
            }
        }
        __syncthreads();

        // ---- LayerNorm stats ----
        {
            float* zA = (float*)(smem + SM_X);
            float2* mv = (float2*)(smem + SM_MV);
#pragma unroll
            for (int l = w; l < GLT; l += 8) {
                float v0 = zA[l * ZPITCH + lane],      v1 = zA[l * ZPITCH + lane + 32];
                float v2 = zA[l * ZPITCH + lane + 64], v3 = zA[l * ZPITCH + lane + 96];
                float s = v0 + v1 + v2 + v3;
                float q = fmaf(v0, v0, fmaf(v1, v1, fmaf(v2, v2, v3 * v3)));
#pragma unroll
                for (int off = 16; off > 0; off >>= 1) {
                    s += __shfl_xor_sync(0xffffffffu, s, off);
                    q += __shfl_xor_sync(0xffffffffu, q, off);
                }
                if (lane == 0) {
                    float m   = s * (1.0f / H_DIM);
                    float var = q * (1.0f / H_DIM) - m * m;
                    mv[l] = make_float2(m, rsqrtf(var + 1e-5f));
                }
            }
        }
        __syncthreads();

        // ---- normalize + write back ----
        {
            int ch = tid & 127, lh = tid >> 7;
            float* zA = (float*)(smem + SM_X);
            float2* mv = (float2*)(smem + SM_MV);
            float gam = __ldg(ln_g + layer * H_DIM + ch);
            float bet = __ldg(ln_b + layer * H_DIM + ch);
            float r[32];
#pragma unroll
            for (int i = 0; i < 32; i++) {
                int l = lh * 32 + i;
                float2 m = mv[l];
                r[i] = fmaf((zA[l * ZPITCH + ch] - m.x) * m.y, gam, bet);
            }
            float4* wp = (float4*)(g_h + (b * H_DIM + ch) * L_SEQ + l0 + lh * 32);
#pragma unroll
            for (int i = 0; i < 8; i++) wp[i] = ((float4*)r)[i];
        }
    }
}

// ---------------- mean over L ----------------
__global__ void pool_kernel() {
    int seq = blockIdx.x;
    int t   = threadIdx.x;
    const float4* r = (const float4*)(g_h + seq * L_SEQ);
    float s = 0.f;
    for (int i = t; i < L_SEQ / 4; i += 256) {
        float4 v = r[i];
        s += v.x + v.y + v.z + v.w;
    }
    __shared__ float sm[256];
    sm[t] = s;
    __syncthreads();
    for (int off = 128; off > 0; off >>= 1) {
        if (t < off) sm[t] += sm[t + off];
        __syncthreads();
    }
    if (t == 0) g_pooled[seq] = sm[0] * (1.f / L_SEQ);
}

// ---------------- head ----------------
__global__ void head_kernel(const float* __restrict__ head_W,
                            const float* __restrict__ head_b,
                            float* __restrict__ out) {
    int t = threadIdx.x;
    if (t >= B_SZ * D_OUT) return;
    int b = t / D_OUT, o = t % D_OUT;
    float s = head_b[o];
    for (int h = 0; h < H_DIM; h++)
        s = fmaf(g_pooled[b * H_DIM + h], head_W[h * D_OUT + o], s);
    out[t] = s;
}

// ---------------- launch ----------------
extern "C" void kernel_launch(void* const* d_in, const int* in_sizes, int n_in,
                              void* d_out, int out_size) {
    const float* x          = (const float*)d_in[0];
    const float* enc_W      = (const float*)d_in[1];
    const float* enc_b      = (const float*)d_in[2];
    const float* log_dt     = (const float*)d_in[3];
    const float* C_re       = (const float*)d_in[4];
    const float* C_im       = (const float*)d_in[5];
    const float* log_A_real = (const float*)d_in[6];
    const float* A_imag     = (const float*)d_in[7];
    const float* Dvec       = (const float*)d_in[8];
    const float* out_W      = (const float*)d_in[9];
    const float* out_b      = (const float*)d_in[10];
    const float* ln_g       = (const float*)d_in[11];
    const float* ln_b       = (const float*)d_in[12];
    const float* head_W     = (const float*)d_in[13];
    const float* head_b     = (const float*)d_in[14];
    float* out = (float*)d_out;

    static int smem_set = 0;
    if (!smem_set) {
        cudaFuncSetAttribute(glu_mma_kernel,
                             cudaFuncAttributeMaxDynamicSharedMemorySize, SMEM_MMA);
        smem_set = 1;
    }

    param_kernel<<<(NL * H_DIM * NC + 127) / 128, 128>>>(log_dt, C_re, C_im,
                                                         log_A_real, A_imag);
    wsplit_kernel<<<(NL * 2 * H_DIM * H_DIM + 255) / 256, 256>>>(out_W);
    enc_kernel<<<(NSEQ * (L_SEQ / 4)) / 256, 256>>>(x, enc_W, enc_b);

    for (int layer = 0; layer < NL; layer++) {
        pass1_kernel<<<(NSEQ * (CHUNKS - 1) * 4) / 128, 128>>>(layer);
        pass2_kernel<<<(NSEQ * CHUNKS * 4) / 128, 128>>>(layer, Dvec);
        glu_mma_kernel<<<B_SZ * 16, 256, SMEM_MMA>>>(layer, out_b, ln_g, ln_b);
    }

    pool_kernel<<<NSEQ, 256>>>();
    head_kernel<<<1, 64>>>(head_W, head_b, out);
}

// round 9
// speedup vs baseline: 1.3317x; 1.1281x over previous
#include <cuda_runtime.h>
#include <cuda_bf16.h>
#include <math.h>

#define B_SZ   32
#define D_IN   2
#define L_SEQ  4096
#define H_DIM  128
#define NL     6
#define NC     32
#define D_OUT  2
#define NSEQ   (B_SZ * H_DIM)        // 4096
#define CHUNKS 16
#define CHLEN  (L_SEQ / CHUNKS)      // 256
#define SPT    8
#define NG     (SPT / 2)

typedef unsigned long long u64;
typedef unsigned int u32;

// ---------------- f32x2 helpers ----------------
__device__ __forceinline__ u64 pk(float lo, float hi) {
    u64 r;
    asm("mov.b64 %0, {%1, %2};" : "=l"(r) : "r"(__float_as_uint(lo)), "r"(__float_as_uint(hi)));
    return r;
}
__device__ __forceinline__ void upk(u64 a, float& lo, float& hi) {
    u32 x, y;
    asm("mov.b64 {%0, %1}, %2;" : "=r"(x), "=r"(y) : "l"(a));
    lo = __uint_as_float(x); hi = __uint_as_float(y);
}
__device__ __forceinline__ u64 fma2(u64 a, u64 b, u64 c) {
    u64 d;
    asm("fma.rn.f32x2 %0, %1, %2, %3;" : "=l"(d) : "l"(a), "l"(b), "l"(c));
    return d;
}
__device__ __forceinline__ u64 mul2(u64 a, u64 b) {
    u64 d;
    asm("mul.rn.f32x2 %0, %1, %2;" : "=l"(d) : "l"(a), "l"(b));
    return d;
}

// ---------------- tensor-core helpers (baseline sm_103 ISA) ----------------
__device__ __forceinline__ unsigned smaddr(const void* p) {
    unsigned a;
    asm("{ .reg .u64 t; cvta.to.shared.u64 t, %1; cvt.u32.u64 %0, t; }" : "=r"(a) : "l"(p));
    return a;
}
__device__ __forceinline__ void ldm_x4(u32& r0, u32& r1, u32& r2, u32& r3, unsigned addr) {
    asm volatile("ldmatrix.sync.aligned.m8n8.x4.shared.b16 {%0,%1,%2,%3}, [%4];"
                 : "=r"(r0), "=r"(r1), "=r"(r2), "=r"(r3) : "r"(addr));
}
__device__ __forceinline__ void mma_bf16(float* c, u32 a0, u32 a1, u32 a2, u32 a3,
                                         u32 b0, u32 b1) {
    asm volatile(
        "mma.sync.aligned.m16n8k16.row.col.f32.bf16.bf16.f32 "
        "{%0,%1,%2,%3}, {%4,%5,%6,%7}, {%8,%9}, {%0,%1,%2,%3};"
        : "+f"(c[0]), "+f"(c[1]), "+f"(c[2]), "+f"(c[3])
        : "r"(a0), "r"(a1), "r"(a2), "r"(a3), "r"(b0), "r"(b1));
}
__device__ __forceinline__ u32 bf16x2pk(float lo, float hi) {
    u32 r;
    asm("cvt.rn.bf16x2.f32 %0, %1, %2;" : "=r"(r) : "f"(hi), "f"(lo));
    return r;
}

// smem layout for glu_mma v2 (dynamic). Pitch 272B -> conflict-free ldmatrix.
#define WPITCH 272
#define SM_W   0                    // 256 x 272 = 69632 (Whi, then Wlo; zAG overlay)
#define SM_AHI 69632                // 64 x 272 = 17408
#define SM_ALO 87040                // 17408
#define SM_MV  104448               // 64 x float2
#define SMEM_MMA 104960
#define ZPITCH 132                  // floats (zAG overlay on SM_W)

#define GLT 64                      // l-tile
#define TILES_PER_BLK 4

// ---------------- scratch ----------------
__device__ float  g_h[NSEQ * L_SEQ];
__device__ float  g_y[NSEQ * L_SEQ];
__device__ float2 g_E[NSEQ * (CHUNKS - 1) * NC];
__device__ float  g_par[NL * 6 * H_DIM * NC];
__device__ __nv_bfloat16 g_Whi[NL * 2 * H_DIM * H_DIM];
__device__ __nv_bfloat16 g_Wlo[NL * 2 * H_DIM * H_DIM];
__device__ float  g_pooled[NSEQ];

// ---------------- parameter precompute ----------------
__global__ void param_kernel(const float* __restrict__ log_dt,
                             const float* __restrict__ C_re,
                             const float* __restrict__ C_im,
                             const float* __restrict__ log_A_real,
                             const float* __restrict__ A_imag) {
    int t = blockIdx.x * blockDim.x + threadIdx.x;
    if (t >= NL * H_DIM * NC) return;
    int layer = t / (H_DIM * NC);
    int hn    = t % (H_DIM * NC);
    int h     = hn / NC;

    double dt  = exp((double)log_dt[layer * H_DIM + h]);
    double Are = -exp((double)log_A_real[t]);
    double Aim = (double)A_imag[t];
    double xre = Are * dt, xim = Aim * dt;

    double ex = exp(xre);
    double sy, cy;
    sincos(xim, &sy, &cy);
    double wre = ex * cy, wim = ex * sy;

    double em1re = ex * cy - 1.0;
    double em1im = ex * sy;

    double den = Are * Are + Aim * Aim;
    double fre = (em1re * Are + em1im * Aim) / den;
    double fim = (em1im * Are - em1re * Aim) / den;
    double cre = (double)C_re[t], cim = (double)C_im[t];
    double c2re = 2.0 * (cre * fre - cim * fim);
    double c2im = 2.0 * (cre * fim + cim * fre);

    double pre = exp(xre * (double)CHLEN);
    double ps, pc;
    sincos(xim * (double)CHLEN, &ps, &pc);

    int S = H_DIM * NC;
    int base = layer * 6 * S + hn;
    g_par[base]         = (float)wre;
    g_par[base + S]     = (float)wim;
    g_par[base + 2 * S] = (float)c2re;
    g_par[base + 3 * S] = (float)c2im;
    g_par[base + 4 * S] = (float)(pre * pc);
    g_par[base + 5 * S] = (float)(pre * ps);
}

// ---------------- weight hi/lo bf16 split ----------------
__global__ void wsplit_kernel(const float* __restrict__ out_W) {
    int t = blockIdx.x * blockDim.x + threadIdx.x;
    if (t >= NL * 2 * H_DIM * H_DIM) return;
    float x = out_W[t];
    __nv_bfloat16 hi = __float2bfloat16(x);
    __nv_bfloat16 lo = __float2bfloat16(x - __bfloat162float(hi));
    g_Whi[t] = hi;
    g_Wlo[t] = lo;
}

// ---------------- encoder ----------------
__global__ void enc_kernel(const float* __restrict__ x,
                           const float* __restrict__ enc_W,
                           const float* __restrict__ enc_b) {
    int t = blockIdx.x * blockDim.x + threadIdx.x;
    if (t >= NSEQ * (L_SEQ / 4)) return;
    int l4  = t % (L_SEQ / 4);
    int seq = t / (L_SEQ / 4);
    int b = seq / H_DIM;
    int h = seq % H_DIM;
    float w0 = enc_W[h];
    float w1 = enc_W[H_DIM + h];
    float bb = enc_b[h];
    float4 a = ((const float4*)(x + (b * D_IN + 0) * L_SEQ))[l4];
    float4 c = ((const float4*)(x + (b * D_IN + 1) * L_SEQ))[l4];
    float4 r;
    r.x = fmaf(w1, c.x, fmaf(w0, a.x, bb));
    r.y = fmaf(w1, c.y, fmaf(w0, a.y, bb));
    r.z = fmaf(w1, c.z, fmaf(w0, a.z, bb));
    r.w = fmaf(w1, c.w, fmaf(w0, a.w, bb));
    ((float4*)(g_h + seq * L_SEQ))[l4] = r;
}

// ---------------- pass 1 ----------------
__global__ void pass1_kernel(int layer) {
    int gid  = blockIdx.x * blockDim.x + threadIdx.x;
    int quarter = gid & 3;
    int pair = gid >> 2;
    int chunk = pair % (CHUNKS - 1);
    int seq   = pair / (CHUNKS - 1);
    int h = seq % H_DIM;

    const float* par = g_par + layer * 6 * H_DIM * NC;
    int S  = H_DIM * NC;
    int pb = h * NC + quarter * SPT;

    u64 wre2[NG], wim2[NG], nwim2[NG], sre2[NG], sim2[NG];
#pragma unroll
    for (int g = 0; g < NG; g++) {
        float2 wr = *(const float2*)(par + pb + 2 * g);
        float2 wi = *(const float2*)(par + S + pb + 2 * g);
        wre2[g]  = pk(wr.x, wr.y);
        wim2[g]  = pk(wi.x, wi.y);
        nwim2[g] = pk(-wi.x, -wi.y);
        sre2[g] = 0ull; sim2[g] = 0ull;
    }

    const float4* u4 = (const float4*)(g_h + seq * L_SEQ + chunk * CHLEN);
    for (int l = 0; l < CHLEN / 4; l++) {
        float4 u = u4[l];
        float uu[4] = {u.x, u.y, u.z, u.w};
#pragma unroll
        for (int q = 0; q < 4; q++) {
            u64 u2 = pk(uu[q], uu[q]);
#pragma unroll
            for (int g = 0; g < NG; g++) {
                u64 nr = fma2(nwim2[g], sim2[g], fma2(wre2[g], sre2[g], u2));
                u64 ni = fma2(wre2[g], sim2[g], mul2(wim2[g], sre2[g]));
                sre2[g] = nr; sim2[g] = ni;
            }
        }
    }

    float2* E = g_E + (seq * (CHUNKS - 1) + chunk) * NC + quarter * SPT;
#pragma unroll
    for (int g = 0; g < NG; g++) {
        float r0, r1, i0, i1;
        upk(sre2[g], r0, r1);
        upk(sim2[g], i0, i1);
        E[2 * g]     = make_float2(r0, i0);
        E[2 * g + 1] = make_float2(r1, i1);
    }
}

// ---------------- pass 2 ----------------
__global__ void pass2_kernel(int layer, const float* __restrict__ Dvec) {
    int gid  = blockIdx.x * blockDim.x + threadIdx.x;
    int quarter = gid & 3;
    int rest = gid >> 2;
    int chunk = rest % CHUNKS;
    int seq   = rest / CHUNKS;
    int h = seq % H_DIM;

    const float* par = g_par + layer * 6 * H_DIM * NC;
    int S  = H_DIM * NC;
    int pb = h * NC + quarter * SPT;

    u64 sre2[NG], sim2[NG];
#pragma unroll
    for (int g = 0; g < NG; g++) { sre2[g] = 0ull; sim2[g] = 0ull; }

    if (chunk > 0) {
        u64 wpre2[NG], wpim2[NG], nwpim2[NG];
#pragma unroll
        for (int g = 0; g < NG; g++) {
            float2 wr = *(const float2*)(par + 4 * S + pb + 2 * g);
            float2 wi = *(const float2*)(par + 5 * S + pb + 2 * g);
            wpre2[g]  = pk(wr.x, wr.y);
            wpim2[g]  = pk(wi.x, wi.y);
            nwpim2[g] = pk(-wi.x, -wi.y);
        }
        for (int c = 0; c < chunk; c++) {
            const float2* E = g_E + (seq * (CHUNKS - 1) + c) * NC + quarter * SPT;
#pragma unroll
            for (int g = 0; g < NG; g++) {
                float2 e0 = E[2 * g], e1 = E[2 * g + 1];
                u64 re2 = pk(e0.x, e1.x);
                u64 im2 = pk(e0.y, e1.y);
                u64 nr = fma2(wpre2[g], sre2[g], fma2(nwpim2[g], sim2[g], re2));
                u64 ni = fma2(wpre2[g], sim2[g], fma2(wpim2[g], sre2[g], im2));
                sre2[g] = nr; sim2[g] = ni;
            }
        }
    }

    u64 wre2[NG], wim2[NG], nwim2[NG], cr2[NG], nci2[NG];
#pragma unroll
    for (int g = 0; g < NG; g++) {
        float2 wr = *(const float2*)(par + pb + 2 * g);
        float2 wi = *(const float2*)(par + S + pb + 2 * g);
        float2 cr = *(const float2*)(par + 2 * S + pb + 2 * g);
        float2 ci = *(const float2*)(par + 3 * S + pb + 2 * g);
        wre2[g]  = pk(wr.x, wr.y);
        wim2[g]  = pk(wi.x, wi.y);
        nwim2[g] = pk(-wi.x, -wi.y);
        cr2[g]   = pk(cr.x, cr.y);
        nci2[g]  = pk(-ci.x, -ci.y);
    }
    float Dh = Dvec[layer * H_DIM + h];

    const float4* u4 = (const float4*)(g_h + seq * L_SEQ + chunk * CHLEN);
    float*        yp = g_y + seq * L_SEQ + chunk * CHLEN;

    int  q1 = quarter & 1;
    bool q2 = (quarter & 2) != 0;

    for (int l = 0; l < CHLEN / 4; l++) {
        float4 u = u4[l];
        float uu[4] = {u.x, u.y, u.z, u.w};
        float s[4];
#pragma unroll
        for (int q = 0; q < 4; q++) {
            float uv = uu[q];
            u64 u2 = pk(uv, uv);
            u64 acc2 = 0ull;
#pragma unroll
            for (int g = 0; g < NG; g++) {
                u64 nr = fma2(nwim2[g], sim2[g], fma2(wre2[g], sre2[g], u2));
                u64 ni = fma2(wre2[g], sim2[g], mul2(wim2[g], sre2[g]));
                sre2[g] = nr; sim2[g] = ni;
                acc2 = fma2(cr2[g], nr, acc2);
                acc2 = fma2(nci2[g], ni, acc2);
            }
            float alo, ahi;
            upk(acc2, alo, ahi);
            s[q] = alo + ahi;
        }
        float sA = q1 ? s[1] : s[0];
        float sB = q1 ? s[0] : s[1];
        float sC = q1 ? s[3] : s[2];
        float sD = q1 ? s[2] : s[3];
        float p0 = sA + __shfl_xor_sync(0xffffffffu, sB, 1);
        float p1 = sC + __shfl_xor_sync(0xffffffffu, sD, 1);
        float send2 = q2 ? p0 : p1;
        float tot = (q2 ? p1 : p0) + __shfl_xor_sync(0xffffffffu, send2, 2);
        float ua = q1 ? uu[1] : uu[0];
        float ub = q1 ? uu[3] : uu[2];
        float um = q2 ? ub : ua;
        float yv = fmaf(um, Dh, tot);
        float gl = 0.5f * yv * (1.f + erff(yv * 0.7071067811865476f));
        yp[4 * l + quarter] = gl;
    }
}

// ======== GLU via mma.sync bf16 split, 2 blocks/SM, W restaged per tile ========
__global__ void __launch_bounds__(256, 2) glu_mma_kernel(int layer,
                           const float* __restrict__ out_b,
                           const float* __restrict__ ln_g,
                           const float* __restrict__ ln_b) {
    extern __shared__ char smem[];
    unsigned sb = smaddr(smem);
    int tid = threadIdx.x;
    int w = tid >> 5, lane = tid & 31;

    int b   = blockIdx.x >> 4;
    int seg = blockIdx.x & 15;

    int mbase = (w & 3) * 16;
    int nbase = (w >> 2) * 128;
    int sel   = lane >> 3;
    int arow  = mbase + (lane & 7) + (sel & 1) * 8;
    int akadd = (sel >> 1) * 8;
    int brow0 = (lane & 7) + (sel >> 1) * 8;
    int bkadd = (sel & 1) * 8;

    const uint4* whi_g = (const uint4*)(g_Whi + layer * 2 * H_DIM * H_DIM);
    const uint4* wlo_g = (const uint4*)(g_Wlo + layer * 2 * H_DIM * H_DIM);

    for (int tl = 0; tl < TILES_PER_BLK; tl++) {
        int l0 = seg * 256 + tl * 64;
        __syncthreads();   // previous tile's epilogue done (zAG overlay freed)

        // ---- stage Whi + Y hi/lo ----
#pragma unroll
        for (int it = 0; it < 16; it++) {
            int idx = tid + it * 256;
            int o = idx >> 4, c = idx & 15;
            *(uint4*)(smem + SM_W + o * WPITCH + c * 16) = __ldg(whi_g + idx);
        }
#pragma unroll
        for (int it = 0; it < 16; it++) {
            int idx = tid + it * 256;          // 64 l x 64 kpairs
            int l = idx & 63, kp = idx >> 6;
            const float* r0 = g_y + (b * H_DIM + 2 * kp) * L_SEQ + l0;
            const float* r1 = r0 + L_SEQ;
            float f0 = __ldg(r0 + l);
            float f1 = __ldg(r1 + l);
            float h0 = __bfloat162float(__float2bfloat16(f0));
            float h1 = __bfloat162float(__float2bfloat16(f1));
            *(u32*)(smem + SM_AHI + l * WPITCH + kp * 4) = bf16x2pk(f0, f1);
            *(u32*)(smem + SM_ALO + l * WPITCH + kp * 4) = bf16x2pk(f0 - h0, f1 - h1);
        }
        __syncthreads();

        float acc[16][4];
#pragma unroll
        for (int n = 0; n < 16; n++)
#pragma unroll
            for (int j = 0; j < 4; j++) acc[n][j] = 0.f;

        // ---- phase A: (Ahi + Alo) x Whi, Bhi frags loaded once per ks ----
#pragma unroll
        for (int ks = 0; ks < 8; ks++) {
            u32 bf[8][4];
#pragma unroll
            for (int nt2 = 0; nt2 < 8; nt2++) {
                int nrow = nbase + nt2 * 16 + brow0;
                ldm_x4(bf[nt2][0], bf[nt2][1], bf[nt2][2], bf[nt2][3],
                       sb + SM_W + nrow * WPITCH + (ks * 16 + bkadd) * 2);
            }
            u32 a0, a1, a2, a3;
            ldm_x4(a0, a1, a2, a3,
                   sb + SM_AHI + arow * WPITCH + (ks * 16 + akadd) * 2);
#pragma unroll
            for (int nt2 = 0; nt2 < 8; nt2++) {
                mma_bf16(acc[2 * nt2],     a0, a1, a2, a3, bf[nt2][0], bf[nt2][1]);
                mma_bf16(acc[2 * nt2 + 1], a0, a1, a2, a3, bf[nt2][2], bf[nt2][3]);
            }
            ldm_x4(a0, a1, a2, a3,
                   sb + SM_ALO + arow * WPITCH + (ks * 16 + akadd) * 2);
#pragma unroll
            for (int nt2 = 0; nt2 < 8; nt2++) {
                mma_bf16(acc[2 * nt2],     a0, a1, a2, a3, bf[nt2][0], bf[nt2][1]);
                mma_bf16(acc[2 * nt2 + 1], a0, a1, a2, a3, bf[nt2][2], bf[nt2][3]);
            }
        }
        __syncthreads();   // phase A done reading Whi

        // ---- restage W = Wlo ----
#pragma unroll
        for (int it = 0; it < 16; it++) {
            int idx = tid + it * 256;
            int o = idx >> 4, c = idx & 15;
            *(uint4*)(smem + SM_W + o * WPITCH + c * 16) = __ldg(wlo_g + idx);
        }
        __syncthreads();

        // ---- phase B: Ahi x Wlo ----
#pragma unroll
        for (int ks = 0; ks < 8; ks++) {
            u32 a0, a1, a2, a3;
            ldm_x4(a0, a1, a2, a3,
                   sb + SM_AHI + arow * WPITCH + (ks * 16 + akadd) * 2);
#pragma unroll
            for (int nt2 = 0; nt2 < 8; nt2++) {
                u32 b0, b1, b2, b3;
                int nrow = nbase + nt2 * 16 + brow0;
                ldm_x4(b0, b1, b2, b3,
                       sb + SM_W + nrow * WPITCH + (ks * 16 + bkadd) * 2);
                mma_bf16(acc[2 * nt2],     a0, a1, a2, a3, b0, b1);
                mma_bf16(acc[2 * nt2 + 1], a0, a1, a2, a3, b2, b3);
            }
        }
        __syncthreads();   // W region free -> zAG overlay

        // ---- scatter frags (+bias) to zAG[sel][l][o] (overlay SM_W) ----
        {
            float* zbase = (float*)(smem + SM_W) + (w >> 2) * GLT * ZPITCH;
            const float* ob = out_b + layer * 2 * H_DIM + nbase;
            int lrow = mbase + (lane >> 2);
            int ncol = 2 * (lane & 3);
#pragma unroll
            for (int nt = 0; nt < 16; nt++) {
                int n = nt * 8 + ncol;
                float b0 = __ldg(ob + n), b1 = __ldg(ob + n + 1);
                *(float2*)(zbase + lrow * ZPITCH + n) =
                    make_float2(acc[nt][0] + b0, acc[nt][1] + b1);
                *(float2*)(zbase + (lrow + 8) * ZPITCH + n) =
                    make_float2(acc[nt][2] + b0, acc[nt][3] + b1);
            }
        }
        __syncthreads();

        // ---- GLU + residual (in place into zA) ----
        {
            int ch = tid & 127, lh = tid >> 7;
            float* zA = (float*)(smem + SM_W);
            float* zG = zA + GLT * ZPITCH;
            const float* hp = g_h + (b * H_DIM + ch) * L_SEQ + l0 + lh * 32;
            float hv[32];
#pragma unroll
            for (int i = 0; i < 8; i++) ((float4*)hv)[i] = __ldg((const float4*)hp + i);
#pragma unroll
            for (int i = 0; i < 32; i++) {
                int l = lh * 32 + i;
                float a = zA[l * ZPITCH + ch];
                float g = zG[l * ZPITCH + ch];
                zA[l * ZPITCH + ch] = fmaf(a, 1.f / (1.f + expf(-g)), hv[i]);
            }
        }
        __syncthreads();

        // ---- LayerNorm stats ----
        {
            float* zA = (float*)(smem + SM_W);
            float2* mv = (float2*)(smem + SM_MV);
#pragma unroll
            for (int l = w; l < GLT; l += 8) {
                float v0 = zA[l * ZPITCH + lane],      v1 = zA[l * ZPITCH + lane + 32];
                float v2 = zA[l * ZPITCH + lane + 64], v3 = zA[l * ZPITCH + lane + 96];
                float s = v0 + v1 + v2 + v3;
                float q = fmaf(v0, v0, fmaf(v1, v1, fmaf(v2, v2, v3 * v3)));
#pragma unroll
                for (int off = 16; off > 0; off >>= 1) {
                    s += __shfl_xor_sync(0xffffffffu, s, off);
                    q += __shfl_xor_sync(0xffffffffu, q, off);
                }
                if (lane == 0) {
                    float m   = s * (1.0f / H_DIM);
                    float var = q * (1.0f / H_DIM) - m * m;
                    mv[l] = make_float2(m, rsqrtf(var + 1e-5f));
                }
            }
        }
        __syncthreads();

        // ---- normalize + write back ----
        {
            int ch = tid & 127, lh = tid >> 7;
            float* zA = (float*)(smem + SM_W);
            float2* mv = (float2*)(smem + SM_MV);
            float gam = __ldg(ln_g + layer * H_DIM + ch);
            float bet = __ldg(ln_b + layer * H_DIM + ch);
            float r[32];
#pragma unroll
            for (int i = 0; i < 32; i++) {
                int l = lh * 32 + i;
                float2 m = mv[l];
                r[i] = fmaf((zA[l * ZPITCH + ch] - m.x) * m.y, gam, bet);
            }
            float4* wp = (float4*)(g_h + (b * H_DIM + ch) * L_SEQ + l0 + lh * 32);
#pragma unroll
            for (int i = 0; i < 8; i++) wp[i] = ((float4*)r)[i];
        }
    }
}

// ---------------- mean over L ----------------
__global__ void pool_kernel() {
    int seq = blockIdx.x;
    int t   = threadIdx.x;
    const float4* r = (const float4*)(g_h + seq * L_SEQ);
    float s = 0.f;
    for (int i = t; i < L_SEQ / 4; i += 256) {
        float4 v = r[i];
        s += v.x + v.y + v.z + v.w;
    }
    __shared__ float sm[256];
    sm[t] = s;
    __syncthreads();
    for (int off = 128; off > 0; off >>= 1) {
        if (t < off) sm[t] += sm[t + off];
        __syncthreads();
    }
    if (t == 0) g_pooled[seq] = sm[0] * (1.f / L_SEQ);
}

// ---------------- head ----------------
__global__ void head_kernel(const float* __restrict__ head_W,
                            const float* __restrict__ head_b,
                            float* __restrict__ out) {
    int t = threadIdx.x;
    if (t >= B_SZ * D_OUT) return;
    int b = t / D_OUT, o = t % D_OUT;
    float s = head_b[o];
    for (int h = 0; h < H_DIM; h++)
        s = fmaf(g_pooled[b * H_DIM + h], head_W[h * D_OUT + o], s);
    out[t] = s;
}

// ---------------- launch ----------------
extern "C" void kernel_launch(void* const* d_in, const int* in_sizes, int n_in,
                              void* d_out, int out_size) {
    const float* x          = (const float*)d_in[0];
    const float* enc_W      = (const float*)d_in[1];
    const float* enc_b      = (const float*)d_in[2];
    const float* log_dt     = (const float*)d_in[3];
    const float* C_re       = (const float*)d_in[4];
    const float* C_im       = (const float*)d_in[5];
    const float* log_A_real = (const float*)d_in[6];
    const float* A_imag     = (const float*)d_in[7];
    const float* Dvec       = (const float*)d_in[8];
    const float* out_W      = (const float*)d_in[9];
    const float* out_b      = (const float*)d_in[10];
    const float* ln_g       = (const float*)d_in[11];
    const float* ln_b       = (const float*)d_in[12];
    const float* head_W     = (const float*)d_in[13];
    const float* head_b     = (const float*)d_in[14];
    float* out = (float*)d_out;

    cudaFuncSetAttribute(glu_mma_kernel,
                         cudaFuncAttributeMaxDynamicSharedMemorySize, SMEM_MMA);

    param_kernel<<<(NL * H_DIM * NC + 127) / 128, 128>>>(log_dt, C_re, C_im,
                                                         log_A_real, A_imag);
    wsplit_kernel<<<(NL * 2 * H_DIM * H_DIM + 255) / 256, 256>>>(out_W);
    enc_kernel<<<(NSEQ * (L_SEQ / 4)) / 256, 256>>>(x, enc_W, enc_b);

    for (int layer = 0; layer < NL; layer++) {
        pass1_kernel<<<(NSEQ * (CHUNKS - 1) * 4) / 128, 128>>>(layer);
        pass2_kernel<<<(NSEQ * CHUNKS * 4) / 128, 128>>>(layer, Dvec);
        glu_mma_kernel<<<B_SZ * 16, 256, SMEM_MMA>>>(layer, out_b, ln_g, ln_b);
    }

    pool_kernel<<<NSEQ, 256>>>();
    head_kernel<<<1, 64>>>(head_W, head_b, out);
}

// round 11
// speedup vs baseline: 1.3463x; 1.0110x over previous
#include <cuda_runtime.h>
#include <cuda_bf16.h>
#include <math.h>

#define B_SZ   32
#define D_IN   2
#define L_SEQ  4096
#define H_DIM  128
#define NL     6
#define NC     32
#define D_OUT  2
#define NSEQ   (B_SZ * H_DIM)        // 4096
#define CHUNKS 16
#define CHLEN  (L_SEQ / CHUNKS)      // 256
#define SPT    8
#define NG     (SPT / 2)

typedef unsigned long long u64;
typedef unsigned int u32;

// ---------------- f32x2 helpers ----------------
__device__ __forceinline__ u64 pk(float lo, float hi) {
    u64 r;
    asm("mov.b64 %0, {%1, %2};" : "=l"(r) : "r"(__float_as_uint(lo)), "r"(__float_as_uint(hi)));
    return r;
}
__device__ __forceinline__ void upk(u64 a, float& lo, float& hi) {
    u32 x, y;
    asm("mov.b64 {%0, %1}, %2;" : "=r"(x), "=r"(y) : "l"(a));
    lo = __uint_as_float(x); hi = __uint_as_float(y);
}
__device__ __forceinline__ u64 fma2(u64 a, u64 b, u64 c) {
    u64 d;
    asm("fma.rn.f32x2 %0, %1, %2, %3;" : "=l"(d) : "l"(a), "l"(b), "l"(c));
    return d;
}
__device__ __forceinline__ u64 mul2(u64 a, u64 b) {
    u64 d;
    asm("mul.rn.f32x2 %0, %1, %2;" : "=l"(d) : "l"(a), "l"(b));
    return d;
}

// ---------------- tensor-core helpers (baseline sm_103 ISA) ----------------
__device__ __forceinline__ unsigned smaddr(const void* p) {
    unsigned a;
    asm("{ .reg .u64 t; cvta.to.shared.u64 t, %1; cvt.u32.u64 %0, t; }" : "=r"(a) : "l"(p));
    return a;
}
__device__ __forceinline__ void ldm_x4(u32& r0, u32& r1, u32& r2, u32& r3, unsigned addr) {
    asm volatile("ldmatrix.sync.aligned.m8n8.x4.shared.b16 {%0,%1,%2,%3}, [%4];"
                 : "=r"(r0), "=r"(r1), "=r"(r2), "=r"(r3) : "r"(addr));
}
__device__ __forceinline__ void mma_bf16(float* c, u32 a0, u32 a1, u32 a2, u32 a3,
                                         u32 b0, u32 b1) {
    asm volatile(
        "mma.sync.aligned.m16n8k16.row.col.f32.bf16.bf16.f32 "
        "{%0,%1,%2,%3}, {%4,%5,%6,%7}, {%8,%9}, {%0,%1,%2,%3};"
        : "+f"(c[0]), "+f"(c[1]), "+f"(c[2]), "+f"(c[3])
        : "r"(a0), "r"(a1), "r"(a2), "r"(a3), "r"(b0), "r"(b1));
}
__device__ __forceinline__ u32 bf16x2pk(float lo, float hi) {
    u32 r;
    asm("cvt.rn.bf16x2.f32 %0, %1, %2;" : "=r"(r) : "f"(hi), "f"(lo));
    return r;
}

// smem layout for glu_mma (dynamic). Pitch 272B -> conflict-free ldmatrix.
#define WPITCH 272
#define SM_W   0                    // 256 x 272 = 69632 (Whi, then Wlo; zAG overlay)
#define SM_AHI 69632                // 64 x 272 = 17408
#define SM_ALO 87040                // 17408
#define SM_MV  104448               // 64 x float2
#define SMEM_MMA 104960
#define ZPITCH 132                  // floats (zAG overlay on SM_W)

#define GLT 64
#define TILES_PER_BLK 4

// ---------------- scratch ----------------
__device__ float  g_h[NSEQ * L_SEQ];
__device__ float  g_y[NSEQ * L_SEQ];
__device__ float  g_par[NL * 6 * H_DIM * NC];        // wre,wim,c2re,c2im,wpre,wpim
__device__ __nv_bfloat16 g_Whi[NL * 2 * H_DIM * H_DIM];
__device__ __nv_bfloat16 g_Wlo[NL * 2 * H_DIM * H_DIM];
__device__ float  g_pooled[NSEQ];

// ---------------- parameter precompute (double; complex form) ----------------
__global__ void param_kernel(const float* __restrict__ log_dt,
                             const float* __restrict__ C_re,
                             const float* __restrict__ C_im,
                             const float* __restrict__ log_A_real,
                             const float* __restrict__ A_imag) {
    int t = blockIdx.x * blockDim.x + threadIdx.x;
    if (t >= NL * H_DIM * NC) return;
    int layer = t / (H_DIM * NC);
    int hn    = t % (H_DIM * NC);
    int h     = hn / NC;

    double dt  = exp((double)log_dt[layer * H_DIM + h]);
    double Are = -exp((double)log_A_real[t]);
    double Aim = (double)A_imag[t];
    double xre = Are * dt, xim = Aim * dt;

    double ex = exp(xre);
    double sy, cy;
    sincos(xim, &sy, &cy);
    double wre = ex * cy, wim = ex * sy;

    double em1re = ex * cy - 1.0;
    double em1im = ex * sy;

    double den = Are * Are + Aim * Aim;
    double fre = (em1re * Are + em1im * Aim) / den;
    double fim = (em1im * Are - em1re * Aim) / den;
    double cre = (double)C_re[t], cim = (double)C_im[t];
    double c2re = 2.0 * (cre * fre - cim * fim);
    double c2im = 2.0 * (cre * fim + cim * fre);

    double pre = exp(xre * (double)CHLEN);
    double ps, pc;
    sincos(xim * (double)CHLEN, &ps, &pc);

    int S = H_DIM * NC;
    int base = layer * 6 * S + hn;
    g_par[base]         = (float)wre;
    g_par[base + S]     = (float)wim;
    g_par[base + 2 * S] = (float)c2re;
    g_par[base + 3 * S] = (float)c2im;
    g_par[base + 4 * S] = (float)(pre * pc);
    g_par[base + 5 * S] = (float)(pre * ps);
}

// ---------------- weight hi/lo bf16 split ----------------
__global__ void wsplit_kernel(const float* __restrict__ out_W) {
    int t = blockIdx.x * blockDim.x + threadIdx.x;
    if (t >= NL * 2 * H_DIM * H_DIM) return;
    float x = out_W[t];
    __nv_bfloat16 hi = __float2bfloat16(x);
    __nv_bfloat16 lo = __float2bfloat16(x - __bfloat162float(hi));
    g_Whi[t] = hi;
    g_Wlo[t] = lo;
}

// ---------------- encoder ----------------
__global__ void enc_kernel(const float* __restrict__ x,
                           const float* __restrict__ enc_W,
                           const float* __restrict__ enc_b) {
    int t = blockIdx.x * blockDim.x + threadIdx.x;
    if (t >= NSEQ * (L_SEQ / 4)) return;
    int l4  = t % (L_SEQ / 4);
    int seq = t / (L_SEQ / 4);
    int b = seq / H_DIM;
    int h = seq % H_DIM;
    float w0 = enc_W[h];
    float w1 = enc_W[H_DIM + h];
    float bb = enc_b[h];
    float4 a = ((const float4*)(x + (b * D_IN + 0) * L_SEQ))[l4];
    float4 c = ((const float4*)(x + (b * D_IN + 1) * L_SEQ))[l4];
    float4 r;
    r.x = fmaf(w1, c.x, fmaf(w0, a.x, bb));
    r.y = fmaf(w1, c.y, fmaf(w0, a.y, bb));
    r.z = fmaf(w1, c.z, fmaf(w0, a.z, bb));
    r.w = fmaf(w1, c.w, fmaf(w0, a.w, bb));
    ((float4*)(g_h + seq * L_SEQ))[l4] = r;
}

// ===== fused SSM: pass1 (chunk states -> smem E) + pass2 (full recurrence) =====
// One block per sequence. 64 threads = 16 chunks x 4 quarters; 8 states/thread
// as 4 f32x2 groups. E lives in 4KB smem; no inter-kernel barrier.
__global__ void __launch_bounds__(64) ssm_kernel(int layer,
                                                 const float* __restrict__ Dvec) {
    __shared__ float2 E[CHUNKS][NC];   // (re, im) chunk-end states

    int t = threadIdx.x;
    int quarter = t & 3;
    int chunk   = t >> 2;
    int seq = blockIdx.x;
    int h = seq % H_DIM;

    const float* par = g_par + layer * 6 * H_DIM * NC;
    int S  = H_DIM * NC;
    int pb = h * NC + quarter * SPT;

    u64 wre2[NG], wim2[NG], nwim2[NG], sre2[NG], sim2[NG];
#pragma unroll
    for (int g = 0; g < NG; g++) {
        float2 wr = *(const float2*)(par + pb + 2 * g);
        float2 wi = *(const float2*)(par + S + pb + 2 * g);
        wre2[g]  = pk(wr.x, wr.y);
        wim2[g]  = pk(wi.x, wi.y);
        nwim2[g] = pk(-wi.x, -wi.y);
        sre2[g] = 0ull; sim2[g] = 0ull;
    }

    // ---- phase 1: zero-init chunk-local end states ----
    const float4* u4 = (const float4*)(g_h + seq * L_SEQ + chunk * CHLEN);
    for (int l = 0; l < CHLEN / 4; l++) {
        float4 u = u4[l];
        float uu[4] = {u.x, u.y, u.z, u.w};
#pragma unroll
        for (int q = 0; q < 4; q++) {
            u64 u2 = pk(uu[q], uu[q]);
#pragma unroll
            for (int g = 0; g < NG; g++) {
                u64 nr = fma2(nwim2[g], sim2[g], fma2(wre2[g], sre2[g], u2));
                u64 ni = fma2(wre2[g], sim2[g], mul2(wim2[g], sre2[g]));
                sre2[g] = nr; sim2[g] = ni;
            }
        }
    }
#pragma unroll
    for (int g = 0; g < NG; g++) {
        float r0, r1, i0, i1;
        upk(sre2[g], r0, r1);
        upk(sim2[g], i0, i1);
        E[chunk][quarter * SPT + 2 * g]     = make_float2(r0, i0);
        E[chunk][quarter * SPT + 2 * g + 1] = make_float2(r1, i1);
    }
    __syncthreads();

    // ---- phase 2: combine E[0..chunk-1] into init state ----
#pragma unroll
    for (int g = 0; g < NG; g++) { sre2[g] = 0ull; sim2[g] = 0ull; }

    if (chunk > 0) {
        u64 wpre2[NG], wpim2[NG], nwpim2[NG];
#pragma unroll
        for (int g = 0; g < NG; g++) {
            float2 wr = *(const float2*)(par + 4 * S + pb + 2 * g);
            float2 wi = *(const float2*)(par + 5 * S + pb + 2 * g);
            wpre2[g]  = pk(wr.x, wr.y);
            wpim2[g]  = pk(wi.x, wi.y);
            nwpim2[g] = pk(-wi.x, -wi.y);
        }
        for (int c = 0; c < chunk; c++) {
            const float2* Ec = &E[c][quarter * SPT];
#pragma unroll
            for (int g = 0; g < NG; g++) {
                float2 e0 = Ec[2 * g], e1 = Ec[2 * g + 1];
                u64 re2 = pk(e0.x, e1.x);
                u64 im2 = pk(e0.y, e1.y);
                u64 nr = fma2(wpre2[g], sre2[g], fma2(nwpim2[g], sim2[g], re2));
                u64 ni = fma2(wpre2[g], sim2[g], fma2(wpim2[g], sre2[g], im2));
                sre2[g] = nr; sim2[g] = ni;
            }
        }
    }

    // ---- phase 2: full recurrence + projection + D skip + gelu ----
    u64 cr2[NG], nci2[NG];
#pragma unroll
    for (int g = 0; g < NG; g++) {
        float2 cr = *(const float2*)(par + 2 * S + pb + 2 * g);
        float2 ci = *(const float2*)(par + 3 * S + pb + 2 * g);
        cr2[g]  = pk(cr.x, cr.y);
        nci2[g] = pk(-ci.x, -ci.y);
    }
    float Dh = Dvec[layer * H_DIM + h];

    float* yp = g_y + seq * L_SEQ + chunk * CHLEN;

    int  q1 = quarter & 1;
    bool q2 = (quarter & 2) != 0;

    for (int l = 0; l < CHLEN / 4; l++) {
        float4 u = u4[l];
        float uu[4] = {u.x, u.y, u.z, u.w};
        float s[4];
#pragma unroll
        for (int q = 0; q < 4; q++) {
            float uv = uu[q];
            u64 u2 = pk(uv, uv);
            u64 acc2 = 0ull;
#pragma unroll
            for (int g = 0; g < NG; g++) {
                u64 nr = fma2(nwim2[g], sim2[g], fma2(wre2[g], sre2[g], u2));
                u64 ni = fma2(wre2[g], sim2[g], mul2(wim2[g], sre2[g]));
                sre2[g] = nr; sim2[g] = ni;
                acc2 = fma2(cr2[g], nr, acc2);
                acc2 = fma2(nci2[g], ni, acc2);
            }
            float alo, ahi;
            upk(acc2, alo, ahi);
            s[q] = alo + ahi;
        }
        // butterfly transpose-reduce across the 4-lane group
        float sA = q1 ? s[1] : s[0];
        float sB = q1 ? s[0] : s[1];
        float sC = q1 ? s[3] : s[2];
        float sD = q1 ? s[2] : s[3];
        float p0 = sA + __shfl_xor_sync(0xffffffffu, sB, 1);
        float p1 = sC + __shfl_xor_sync(0xffffffffu, sD, 1);
        float send2 = q2 ? p0 : p1;
        float tot = (q2 ? p1 : p0) + __shfl_xor_sync(0xffffffffu, send2, 2);
        float ua = q1 ? uu[1] : uu[0];
        float ub = q1 ? uu[3] : uu[2];
        float um = q2 ? ub : ua;
        float yv = fmaf(um, Dh, tot);
        float gl = 0.5f * yv * (1.f + erff(yv * 0.7071067811865476f));
        yp[4 * l + quarter] = gl;
    }
}

// ======== GLU via mma.sync bf16 split, 2 blocks/SM, W restaged per tile ========
__global__ void __launch_bounds__(256, 2) glu_mma_kernel(int layer,
                           const float* __restrict__ out_b,
                           const float* __restrict__ ln_g,
                           const float* __restrict__ ln_b) {
    extern __shared__ char smem[];
    unsigned sb = smaddr(smem);
    int tid = threadIdx.x;
    int w = tid >> 5, lane = tid & 31;

    int b   = blockIdx.x >> 4;
    int seg = blockIdx.x & 15;

    int mbase = (w & 3) * 16;
    int nbase = (w >> 2) * 128;
    int sel   = lane >> 3;
    int arow  = mbase + (lane & 7) + (sel & 1) * 8;
    int akadd = (sel >> 1) * 8;
    int brow0 = (lane & 7) + (sel >> 1) * 8;
    int bkadd = (sel & 1) * 8;

    const uint4* whi_g = (const uint4*)(g_Whi + layer * 2 * H_DIM * H_DIM);
    const uint4* wlo_g = (const uint4*)(g_Wlo + layer * 2 * H_DIM * H_DIM);

    for (int tl = 0; tl < TILES_PER_BLK; tl++) {
        int l0 = seg * 256 + tl * 64;
        __syncthreads();

        // ---- stage Whi + Y hi/lo ----
#pragma unroll
        for (int it = 0; it < 16; it++) {
            int idx = tid + it * 256;
            int o = idx >> 4, c = idx & 15;
            *(uint4*)(smem + SM_W + o * WPITCH + c * 16) = __ldg(whi_g + idx);
        }
#pragma unroll
        for (int it = 0; it < 16; it++) {
            int idx = tid + it * 256;
            int l = idx & 63, kp = idx >> 6;
            const float* r0 = g_y + (b * H_DIM + 2 * kp) * L_SEQ + l0;
            const float* r1 = r0 + L_SEQ;
            float f0 = __ldg(r0 + l);
            float f1 = __ldg(r1 + l);
            float h0 = __bfloat162float(__float2bfloat16(f0));
            float h1 = __bfloat162float(__float2bfloat16(f1));
            *(u32*)(smem + SM_AHI + l * WPITCH + kp * 4) = bf16x2pk(f0, f1);
            *(u32*)(smem + SM_ALO + l * WPITCH + kp * 4) = bf16x2pk(f0 - h0, f1 - h1);
        }
        __syncthreads();

        float acc[16][4];
#pragma unroll
        for (int n = 0; n < 16; n++)
#pragma unroll
            for (int j = 0; j < 4; j++) acc[n][j] = 0.f;

        // ---- phase A: (Ahi + Alo) x Whi ----
#pragma unroll
        for (int ks = 0; ks < 8; ks++) {
            u32 bf[8][4];
#pragma unroll
            for (int nt2 = 0; nt2 < 8; nt2++) {
                int nrow = nbase + nt2 * 16 + brow0;
                ldm_x4(bf[nt2][0], bf[nt2][1], bf[nt2][2], bf[nt2][3],
                       sb + SM_W + nrow * WPITCH + (ks * 16 + bkadd) * 2);
            }
            u32 a0, a1, a2, a3;
            ldm_x4(a0, a1, a2, a3,
                   sb + SM_AHI + arow * WPITCH + (ks * 16 + akadd) * 2);
#pragma unroll
            for (int nt2 = 0; nt2 < 8; nt2++) {
                mma_bf16(acc[2 * nt2],     a0, a1, a2, a3, bf[nt2][0], bf[nt2][1]);
                mma_bf16(acc[2 * nt2 + 1], a0, a1, a2, a3, bf[nt2][2], bf[nt2][3]);
            }
            ldm_x4(a0, a1, a2, a3,
                   sb + SM_ALO + arow * WPITCH + (ks * 16 + akadd) * 2);
#pragma unroll
            for (int nt2 = 0; nt2 < 8; nt2++) {
                mma_bf16(acc[2 * nt2],     a0, a1, a2, a3, bf[nt2][0], bf[nt2][1]);
                mma_bf16(acc[2 * nt2 + 1], a0, a1, a2, a3, bf[nt2][2], bf[nt2][3]);
            }
        }
        __syncthreads();

        // ---- restage W = Wlo ----
#pragma unroll
        for (int it = 0; it < 16; it++) {
            int idx = tid + it * 256;
            int o = idx >> 4, c = idx & 15;
            *(uint4*)(smem + SM_W + o * WPITCH + c * 16) = __ldg(wlo_g + idx);
        }
        __syncthreads();

        // ---- phase B: Ahi x Wlo ----
#pragma unroll
        for (int ks = 0; ks < 8; ks++) {
            u32 a0, a1, a2, a3;
            ldm_x4(a0, a1, a2, a3,
                   sb + SM_AHI + arow * WPITCH + (ks * 16 + akadd) * 2);
#pragma unroll
            for (int nt2 = 0; nt2 < 8; nt2++) {
                u32 b0, b1, b2, b3;
                int nrow = nbase + nt2 * 16 + brow0;
                ldm_x4(b0, b1, b2, b3,
                       sb + SM_W + nrow * WPITCH + (ks * 16 + bkadd) * 2);
                mma_bf16(acc[2 * nt2],     a0, a1, a2, a3, b0, b1);
                mma_bf16(acc[2 * nt2 + 1], a0, a1, a2, a3, b2, b3);
            }
        }
        __syncthreads();

        // ---- scatter frags (+bias) to zAG (overlay SM_W) ----
        {
            float* zbase = (float*)(smem + SM_W) + (w >> 2) * GLT * ZPITCH;
            const float* ob = out_b + layer * 2 * H_DIM + nbase;
            int lrow = mbase + (lane >> 2);
            int ncol = 2 * (lane & 3);
#pragma unroll
            for (int nt = 0; nt < 16; nt++) {
                int n = nt * 8 + ncol;
                float b0 = __ldg(ob + n), b1 = __ldg(ob + n + 1);
                *(float2*)(zbase + lrow * ZPITCH + n) =
                    make_float2(acc[nt][0] + b0, acc[nt][1] + b1);
                *(float2*)(zbase + (lrow + 8) * ZPITCH + n) =
                    make_float2(acc[nt][2] + b0, acc[nt][3] + b1);
            }
        }
        __syncthreads();

        // ---- GLU + residual ----
        {
            int ch = tid & 127, lh = tid >> 7;
            float* zA = (float*)(smem + SM_W);
            float* zG = zA + GLT * ZPITCH;
            const float* hp = g_h + (b * H_DIM + ch) * L_SEQ + l0 + lh * 32;
            float hv[32];
#pragma unroll
            for (int i = 0; i < 8; i++) ((float4*)hv)[i] = __ldg((const float4*)hp + i);
#pragma unroll
            for (int i = 0; i < 32; i++) {
                int l = lh * 32 + i;
                float a = zA[l * ZPITCH + ch];
                float g = zG[l * ZPITCH + ch];
                zA[l * ZPITCH + ch] = fmaf(a, 1.f / (1.f + expf(-g)), hv[i]);
            }
        }
        __syncthreads();

        // ---- LayerNorm stats ----
        {
            float* zA = (float*)(smem + SM_W);
            float2* mv = (float2*)(smem + SM_MV);
#pragma unroll
            for (int l = w; l < GLT; l += 8) {
                float v0 = zA[l * ZPITCH + lane],      v1 = zA[l * ZPITCH + lane + 32];
                float v2 = zA[l * ZPITCH + lane + 64], v3 = zA[l * ZPITCH + lane + 96];
                float s = v0 + v1 + v2 + v3;
                float q = fmaf(v0, v0, fmaf(v1, v1, fmaf(v2, v2, v3 * v3)));
#pragma unroll
                for (int off = 16; off > 0; off >>= 1) {
                    s += __shfl_xor_sync(0xffffffffu, s, off);
                    q += __shfl_xor_sync(0xffffffffu, q, off);
                }
                if (lane == 0) {
                    float m   = s * (1.0f / H_DIM);
                    float var = q * (1.0f / H_DIM) - m * m;
                    mv[l] = make_float2(m, rsqrtf(var + 1e-5f));
                }
            }
        }
        __syncthreads();

        // ---- normalize + write back ----
        {
            int ch = tid & 127, lh = tid >> 7;
            float* zA = (float*)(smem + SM_W);
            float2* mv = (float2*)(smem + SM_MV);
            float gam = __ldg(ln_g + layer * H_DIM + ch);
            float bet = __ldg(ln_b + layer * H_DIM + ch);
            float r[32];
#pragma unroll
            for (int i = 0; i < 32; i++) {
                int l = lh * 32 + i;
                float2 m = mv[l];
                r[i] = fmaf((zA[l * ZPITCH + ch] - m.x) * m.y, gam, bet);
            }
            float4* wp = (float4*)(g_h + (b * H_DIM + ch) * L_SEQ + l0 + lh * 32);
#pragma unroll
            for (int i = 0; i < 8; i++) wp[i] = ((float4*)r)[i];
        }
    }
}

// ---------------- mean over L ----------------
__global__ void pool_kernel() {
    int seq = blockIdx.x;
    int t   = threadIdx.x;
    const float4* r = (const float4*)(g_h + seq * L_SEQ);
    float s = 0.f;
    for (int i = t; i < L_SEQ / 4; i += 256) {
        float4 v = r[i];
        s += v.x + v.y + v.z + v.w;
    }
    __shared__ float sm[256];
    sm[t] = s;
    __syncthreads();
    for (int off = 128; off > 0; off >>= 1) {
        if (t < off) sm[t] += sm[t + off];
        __syncthreads();
    }
    if (t == 0) g_pooled[seq] = sm[0] * (1.f / L_SEQ);
}

// ---------------- head ----------------
__global__ void head_kernel(const float* __restrict__ head_W,
                            const float* __restrict__ head_b,
                            float* __restrict__ out) {
    int t = threadIdx.x;
    if (t >= B_SZ * D_OUT) return;
    int b = t / D_OUT, o = t % D_OUT;
    float s = head_b[o];
    for (int h = 0; h < H_DIM; h++)
        s = fmaf(g_pooled[b * H_DIM + h], head_W[h * D_OUT + o], s);
    out[t] = s;
}

// ---------------- launch ----------------
extern "C" void kernel_launch(void* const* d_in, const int* in_sizes, int n_in,
                              void* d_out, int out_size) {
    const float* x          = (const float*)d_in[0];
    const float* enc_W      = (const float*)d_in[1];
    const float* enc_b      = (const float*)d_in[2];
    const float* log_dt     = (const float*)d_in[3];
    const float* C_re       = (const float*)d_in[4];
    const float* C_im       = (const float*)d_in[5];
    const float* log_A_real = (const float*)d_in[6];
    const float* A_imag     = (const float*)d_in[7];
    const float* Dvec       = (const float*)d_in[8];
    const float* out_W      = (const float*)d_in[9];
    const float* out_b      = (const float*)d_in[10];
    const float* ln_g       = (const float*)d_in[11];
    const float* ln_b       = (const float*)d_in[12];
    const float* head_W     = (const float*)d_in[13];
    const float* head_b     = (const float*)d_in[14];
    float* out = (float*)d_out;

    cudaFuncSetAttribute(glu_mma_kernel,
                         cudaFuncAttributeMaxDynamicSharedMemorySize, SMEM_MMA);

    param_kernel<<<(NL * H_DIM * NC + 127) / 128, 128>>>(log_dt, C_re, C_im,
                                                         log_A_real, A_imag);
    wsplit_kernel<<<(NL * 2 * H_DIM * H_DIM + 255) / 256, 256>>>(out_W);
    enc_kernel<<<(NSEQ * (L_SEQ / 4)) / 256, 256>>>(x, enc_W, enc_b);

    for (int layer = 0; layer < NL; layer++) {
        ssm_kernel<<<NSEQ, 64>>>(layer, Dvec);
        glu_mma_kernel<<<B_SZ * 16, 256, SMEM_MMA>>>(layer, out_b, ln_g, ln_b);
    }

    pool_kernel<<<NSEQ, 256>>>();
    head_kernel<<<1, 64>>>(head_W, head_b, out);
}